// round 14
// baseline (speedup 1.0000x reference)
#include <cuda_runtime.h>
#include <math.h>
#include <stdint.h>

// Problem constants
#define V_ 50000
#define E_ 300
#define T_ 512
#define U_ 256
#define G_ 768      // 3*U
#define B_ 64
#define C_ 20
#define M_ (B_*T_)  // 32768

// ---------------- static device scratch ----------------
__device__ float g_xw[2][(size_t)M_ * G_];        // input projections per direction
__device__ float g_h1[(size_t)M_ * 2 * U_];       // layer1 h history [B][T][2U]  (write-once/launch)
__device__ float g_h2f[(size_t)2 * B_ * T_ * U_]; // layer2 h history [dir][B][T][U] (write-once/launch)
__device__ float g_h2[B_][2 * U_];                // final states
__device__ unsigned g_flg[2][2][4][T_];           // per-step arrival flags [layer][dir][bblk][step]

__device__ __forceinline__ uint32_t smem_u32(const void* p) {
    uint32_t a;
    asm("{ .reg .u64 t; cvta.to.shared.u64 t, %1; cvt.u32.u64 %0, t; }" : "=r"(a) : "l"(p));
    return a;
}
__device__ __forceinline__ void mma_tf32_16n8k8(float* c, const uint32_t* a, const uint32_t* b) {
    asm volatile(
        "mma.sync.aligned.m16n8k8.row.col.f32.tf32.tf32.f32 "
        "{%0,%1,%2,%3}, {%4,%5,%6,%7}, {%8,%9}, {%0,%1,%2,%3};"
        : "+f"(c[0]), "+f"(c[1]), "+f"(c[2]), "+f"(c[3])
        : "r"(a[0]), "r"(a[1]), "r"(a[2]), "r"(a[3]), "r"(b[0]), "r"(b[1]));
}
__device__ __forceinline__ uint32_t ldcg_u(const float* p) {
    uint32_t v;
    asm volatile("ld.global.cg.b32 %0, [%1];" : "=r"(v) : "l"(p) : "memory");
    return v;
}
__device__ __forceinline__ void stcg_f(float* p, float v) {
    asm volatile("st.global.cg.f32 [%0], %1;" :: "l"(p), "f"(v) : "memory");
}
__device__ __forceinline__ unsigned ld_acq(const unsigned* p) {
    unsigned v;
    asm volatile("ld.acquire.gpu.global.u32 %0, [%1];" : "=r"(v) : "l"(p) : "memory");
    return v;
}
__device__ __forceinline__ void red_rel_add(unsigned* p, unsigned v) {
    asm volatile("red.release.gpu.global.add.u32 [%0], %1;" :: "l"(p), "r"(v) : "memory");
}
#define CP_COMMIT() asm volatile("cp.async.commit_group;" ::: "memory")
#define CP_WAIT(n)  asm volatile("cp.async.wait_group %0;" :: "n"(n) : "memory")

// ---------------- reset flags (16KB) ----------------
__global__ void reset_k() {
    unsigned* f = &g_flg[0][0][0][0];
    const int n = 2 * 2 * 4 * T_;
    for (int i = threadIdx.x + blockIdx.x * blockDim.x; i < n; i += blockDim.x * gridDim.x)
        f[i] = 0u;
}

// ---------------- tf32 mma.sync GEMM, cp.async double-buffered, both dirs in one launch ----------------
#define SA_ 36
#define SB_ 136
#define A_FLOATS (128 * SA_)
#define B_FLOATS (32 * SB_)
#define BUF_FLOATS (A_FLOATS + B_FLOATS)
#define GEMM_SMEM (2 * BUF_FLOATS * 4)

__device__ __forceinline__ void stage_tile(
    uint32_t sa, uint32_t sb, const float* __restrict__ arow_p,
    const float* __restrict__ W, int n0, int k0, int Kreal, int tid)
{
    {
        int aseg0 = (tid & 1) * 4;
        int arow  = tid >> 1;
#pragma unroll
        for (int q = 0; q < 4; q++) {
            int col = k0 + (aseg0 + q) * 4;
            int szf = Kreal - col; szf = szf < 0 ? 0 : (szf > 4 ? 4 : szf);
            int sz = szf * 4;
            const float* src = arow_p + (sz ? col : 0);
            uint32_t dst = sa + (uint32_t)(arow * SA_ + (aseg0 + q) * 4) * 4u;
            asm volatile("cp.async.cg.shared.global [%0], [%1], 16, %2;"
                         :: "r"(dst), "l"(src), "r"(sz) : "memory");
        }
    }
    {
        int krow  = tid >> 3;
        int bseg0 = (tid & 7) * 4;
        int kr = k0 + krow;
        int sz = (kr < Kreal) ? 16 : 0;
        const float* brow_p = W + (size_t)(sz ? kr : 0) * G_ + n0;
#pragma unroll
        for (int q = 0; q < 4; q++) {
            uint32_t dst = sb + (uint32_t)(krow * SB_ + (bseg0 + q) * 4) * 4u;
            asm volatile("cp.async.cg.shared.global [%0], [%1], 16, %2;"
                         :: "r"(dst), "l"(brow_p + (bseg0 + q) * 4), "r"(sz) : "memory");
        }
    }
}

__global__ void __launch_bounds__(256, 2) mma_gemm_k(
    const float* __restrict__ A,
    const float* __restrict__ W0, const float* __restrict__ W1,
    const float* __restrict__ bias0, const float* __restrict__ bias1,
    float* __restrict__ C0, float* __restrict__ C1,
    int Kreal, const int* __restrict__ xidx)
{
    extern __shared__ float smf[];
    const uint32_t sbase = smem_u32(smf);

    const float* W    = blockIdx.z ? W1 : W0;
    const float* bias = blockIdx.z ? bias1 : bias0;
    float*       Cc   = blockIdx.z ? C1 : C0;

    const int tid  = threadIdx.x;
    const int wid  = tid >> 5;
    const int lane = tid & 31;
    const int lq   = lane & 3;
    const int gid  = lane >> 2;
    const int m0 = blockIdx.y * 128;
    const int n0 = blockIdx.x * 128;
    const int m0w = (wid & 3) * 32;
    const int n0w = (wid >> 2) * 64;

    const int arow = tid >> 1;
    const int ridx = xidx ? __ldg(&xidx[m0 + arow]) : (m0 + arow);
    const float* arow_p = A + (size_t)ridx * Kreal;

    float2 bv[8];
#pragma unroll
    for (int nt = 0; nt < 8; nt++)
        bv[nt] = *(const float2*)&bias[n0 + n0w + nt * 8 + lq * 2];

    float cfr[2][8][4];
#pragma unroll
    for (int mt = 0; mt < 2; mt++)
#pragma unroll
        for (int nt = 0; nt < 8; nt++)
#pragma unroll
            for (int j = 0; j < 4; j++) cfr[mt][nt][j] = 0.f;

    const int KT = (Kreal + 31) >> 5;

    stage_tile(sbase, sbase + A_FLOATS * 4u, arow_p, W, n0, 0, Kreal, tid);
    CP_COMMIT();

    for (int kt = 0; kt < KT; kt++) {
        const int cur = kt & 1;
        if (kt + 1 < KT) {
            uint32_t nb = sbase + (uint32_t)(((kt + 1) & 1) * BUF_FLOATS) * 4u;
            stage_tile(nb, nb + A_FLOATS * 4u, arow_p, W, n0, (kt + 1) << 5, Kreal, tid);
            CP_COMMIT();
            CP_WAIT(1);
        } else {
            CP_WAIT(0);
        }
        __syncthreads();

        const float* As_ = smf + cur * BUF_FLOATS;
        const float* Bs_ = As_ + A_FLOATS;

#pragma unroll
        for (int ks = 0; ks < 4; ks++) {
            const int kb = ks * 8;
            uint32_t af[2][4], bf[8][2];
#pragma unroll
            for (int mt = 0; mt < 2; mt++) {
                const float* ap = As_ + (m0w + mt * 16 + gid) * SA_ + kb + lq;
                af[mt][0] = __float_as_uint(ap[0]);
                af[mt][1] = __float_as_uint(ap[8 * SA_]);
                af[mt][2] = __float_as_uint(ap[4]);
                af[mt][3] = __float_as_uint(ap[8 * SA_ + 4]);
            }
#pragma unroll
            for (int nt = 0; nt < 8; nt++) {
                const float* bp = Bs_ + (kb + lq) * SB_ + n0w + nt * 8 + gid;
                bf[nt][0] = __float_as_uint(bp[0]);
                bf[nt][1] = __float_as_uint(bp[4 * SB_]);
            }
#pragma unroll
            for (int mt = 0; mt < 2; mt++)
#pragma unroll
                for (int nt = 0; nt < 8; nt++)
                    mma_tf32_16n8k8(cfr[mt][nt], af[mt], bf[nt]);
        }
        __syncthreads();
    }

#pragma unroll
    for (int mt = 0; mt < 2; mt++) {
        int row = m0 + m0w + mt * 16 + gid;
#pragma unroll
        for (int nt = 0; nt < 8; nt++) {
            int col = n0 + n0w + nt * 8 + lq * 2;
            float2 v0, v1;
            v0.x = cfr[mt][nt][0] + bv[nt].x;
            v0.y = cfr[mt][nt][1] + bv[nt].y;
            v1.x = cfr[mt][nt][2] + bv[nt].x;
            v1.y = cfr[mt][nt][3] + bv[nt].y;
            *(float2*)&Cc[(size_t)row * G_ + col] = v0;
            *(float2*)&Cc[(size_t)(row + 8) * G_ + col] = v1;
        }
    }
}

// ---------------- persistent bidirectional GRU scan — per-step release/acquire flags ----------------
// grid = 64 CTAs: dir(2) x bblk(4, 16 batches) x ublk(8, 32 units). block = 512 (16 warps).
// Producer: h stores (stcg) -> __syncthreads -> tid0 red.release.add(flg[s], 1).
// Consumer (step s): every warp spins on ld.acquire(flg[s-1]) until == 8, then loads its
// A fragments directly from the h history in global memory. hprev lives in a register.
#define PT_STRIDE 100
#define SCAN_SMEM (2 * 4 * 16 * PT_STRIDE * 4)   // 51200 bytes
__global__ void __launch_bounds__(512, 1) scan_k(
    const float* __restrict__ rkf, const float* __restrict__ rbf,
    const float* __restrict__ rkb, const float* __restrict__ rbb,
    int layer)
{
    extern __shared__ float part[];              // [2 parity][4 kg][16 m][PT_STRIDE]

    const int cta  = blockIdx.x;
    const int dir  = cta >> 5;
    const int bblk = (cta >> 3) & 3;
    const int ublk = cta & 7;
    const int b0 = bblk * 16, u0 = ublk * 32;
    const int tid  = threadIdx.x;
    const int wid  = tid >> 5;
    const int lane = tid & 31;
    const int lq   = lane & 3;
    const int gid  = lane >> 2;
    const int kg   = wid & 3;
    const int ng   = wid >> 2;

    const float* rk = dir ? rkb : rkf;
    const float* rb = dir ? rbb : rbf;
    const float* xw = g_xw[dir];
    unsigned* flg = &g_flg[layer - 1][dir][bblk][0];

    // recurrent-weight B fragments in registers (once)
    uint32_t bw[3][8][2];
#pragma unroll
    for (int nt = 0; nt < 3; nt++) {
        int c = ng * 24 + nt * 8 + gid;
        int ncol = (c >> 5) * U_ + u0 + (c & 31);
#pragma unroll
        for (int kt = 0; kt < 8; kt++) {
            int kb = kg * 64 + kt * 8 + lq;
            bw[nt][kt][0] = __float_as_uint(__ldg(&rk[(size_t)kb * G_ + ncol]));
            bw[nt][kt][1] = __float_as_uint(__ldg(&rk[(size_t)(kb + 4) * G_ + ncol]));
        }
    }

    // gate role: thread -> (batch wid, unit lane)
    const float bz  = rb[u0 + lane];
    const float brr = rb[U_ + u0 + lane];
    const float bh  = rb[2 * U_ + u0 + lane];
    float hprev = 0.f;

    for (int s = 0; s < T_; s++) {
        const int t = dir ? (T_ - 1 - s) : s;

        // prefetch xw (in flight under poll/dot)
        const float* xwp = xw + ((size_t)(b0 + wid) * T_ + t) * G_;
        float xz = __ldg(xwp + u0 + lane);
        float xr = __ldg(xwp + U_ + u0 + lane);
        float xh = __ldg(xwp + 2 * U_ + u0 + lane);

        float acc[3][4];
#pragma unroll
        for (int nt = 0; nt < 3; nt++)
#pragma unroll
            for (int j = 0; j < 4; j++) acc[nt][j] = 0.f;

        if (s > 0) {
            // wait for all 8 group CTAs to have published step s-1
            unsigned f;
            do { f = ld_acq(flg + (s - 1)); } while (f < 8u);

            const int tp = dir ? (t + 1) : (t - 1);
            const float *base0, *base1;
            if (layer == 1) {
                base0 = g_h1 + ((size_t)(b0 + gid)     * T_ + tp) * (2 * U_) + dir * U_ + kg * 64 + lq;
                base1 = g_h1 + ((size_t)(b0 + gid + 8) * T_ + tp) * (2 * U_) + dir * U_ + kg * 64 + lq;
            } else {
                base0 = g_h2f + ((size_t)(dir * B_ + b0 + gid)     * T_ + tp) * U_ + kg * 64 + lq;
                base1 = g_h2f + ((size_t)(dir * B_ + b0 + gid + 8) * T_ + tp) * U_ + kg * 64 + lq;
            }
#pragma unroll
            for (int kt = 0; kt < 8; kt++) {
                const int off = kt * 8;
                uint32_t af[4];
                af[0] = ldcg_u(base0 + off);
                af[1] = ldcg_u(base1 + off);
                af[2] = ldcg_u(base0 + off + 4);
                af[3] = ldcg_u(base1 + off + 4);
#pragma unroll
                for (int nt = 0; nt < 3; nt++)
                    mma_tf32_16n8k8(acc[nt], af, bw[nt][kt]);
            }
        }

        // partials -> smem (parity double buffer)
        {
            float* pp = part + (s & 1) * 6400 + kg * 1600;
#pragma unroll
            for (int nt = 0; nt < 3; nt++) {
                int colb = ng * 24 + nt * 8 + 2 * lq;
                *(float2*)&pp[gid * PT_STRIDE + colb]       = make_float2(acc[nt][0], acc[nt][1]);
                *(float2*)&pp[(gid + 8) * PT_STRIDE + colb] = make_float2(acc[nt][2], acc[nt][3]);
            }
        }
        __syncthreads();

        // gates
        {
            float az = bz, ar = brr, ah = bh;
#pragma unroll
            for (int k4 = 0; k4 < 4; k4++) {
                const float* pp = part + (s & 1) * 6400 + k4 * 1600 + wid * PT_STRIDE;
                az += pp[lane];
                ar += pp[32 + lane];
                ah += pp[64 + lane];
            }
            float z  = 1.f / (1.f + expf(-(xz + az)));
            float rg = 1.f / (1.f + expf(-(xr + ar)));
            float hh = tanhf(xh + rg * ah);
            float hn = z * hprev + (1.f - z) * hh;
            hprev = hn;
            if (layer == 1) {
                stcg_f(&g_h1[((size_t)(b0 + wid) * T_ + t) * (2 * U_) + dir * U_ + u0 + lane], hn);
            } else {
                stcg_f(&g_h2f[((size_t)(dir * B_ + b0 + wid) * T_ + t) * U_ + u0 + lane], hn);
                if (s == T_ - 1) g_h2[b0 + wid][dir * U_ + u0 + lane] = hn;
            }
        }
        __syncthreads();                      // all h stores done before arrive

        if (tid == 0 && s != T_ - 1)
            red_rel_add(flg + s, 1u);         // release: publish step s to the group
    }
}

// ---------------- head: softmax(h2 @ wout + bout) ----------------
__global__ void head_k(const float* __restrict__ wout, const float* __restrict__ bout,
                       float* __restrict__ out)
{
    const int b = blockIdx.x, lane = threadIdx.x;
    float acc = 0.f;
    if (lane < C_) {
        acc = bout[lane];
        for (int k = 0; k < 2 * U_; k++)
            acc = fmaf(g_h2[b][k], wout[k * C_ + lane], acc);
    }
    float v = (lane < C_) ? acc : -INFINITY;
    for (int o = 16; o; o >>= 1) v = fmaxf(v, __shfl_xor_sync(0xffffffffu, v, o));
    float e = (lane < C_) ? expf(acc - v) : 0.f;
    float ssum = e;
    for (int o = 16; o; o >>= 1) ssum += __shfl_xor_sync(0xffffffffu, ssum, o);
    if (lane < C_) out[b * C_ + lane] = e / ssum;
}

// ---------------- launch ----------------
extern "C" void kernel_launch(void* const* d_in, const int* in_sizes, int n_in,
                              void* d_out, int out_size)
{
    const int*   x    = (const int*)  d_in[0];
    const float* emb  = (const float*)d_in[1];
    const float* k1f  = (const float*)d_in[2];
    const float* rk1f = (const float*)d_in[3];
    const float* b1f  = (const float*)d_in[4];
    const float* k1b  = (const float*)d_in[5];
    const float* rk1b = (const float*)d_in[6];
    const float* b1b  = (const float*)d_in[7];
    const float* k2f  = (const float*)d_in[8];
    const float* rk2f = (const float*)d_in[9];
    const float* b2f  = (const float*)d_in[10];
    const float* k2b  = (const float*)d_in[11];
    const float* rk2b = (const float*)d_in[12];
    const float* b2b  = (const float*)d_in[13];
    const float* wout = (const float*)d_in[14];
    const float* bout = (const float*)d_in[15];
    float* out = (float*)d_out;

    float *pxw0, *pxw1, *ph1;
    cudaGetSymbolAddress((void**)&pxw0, g_xw);
    pxw1 = pxw0 + (size_t)M_ * G_;
    cudaGetSymbolAddress((void**)&ph1,  g_h1);

    cudaFuncSetAttribute(mma_gemm_k, cudaFuncAttributeMaxDynamicSharedMemorySize, GEMM_SMEM);
    cudaFuncSetAttribute(scan_k,     cudaFuncAttributeMaxDynamicSharedMemorySize, SCAN_SMEM);

    dim3 gg(G_ / 128, M_ / 128, 2);   // (6, 256, dir)

    // 0) reset per-step flags
    reset_k<<<8, 512>>>();

    // 1) layer-1 input projections, both dirs in one launch, gather fused
    mma_gemm_k<<<gg, 256, GEMM_SMEM>>>(emb, k1f, k1b, b1f, b1b, pxw0, pxw1, E_, x);

    // 2) layer-1 bidirectional scan -> g_h1
    scan_k<<<64, 512, SCAN_SMEM>>>(rk1f, b1f + G_, rk1b, b1b + G_, 1);

    // 3) layer-2 input projections, both dirs
    mma_gemm_k<<<gg, 256, GEMM_SMEM>>>(ph1, k2f, k2b, b2f, b2b, pxw0, pxw1, 2 * U_, (const int*)nullptr);

    // 4) layer-2 bidirectional scan -> g_h2
    scan_k<<<64, 512, SCAN_SMEM>>>(rk2f, b2f + G_, rk2b, b2b + G_, 2);

    // 5) output head
    head_k<<<B_, 32>>>(wout, bout, out);
}

// round 15
// speedup vs baseline: 1.2689x; 1.2689x over previous
#include <cuda_runtime.h>
#include <math.h>
#include <stdint.h>

// Problem constants
#define V_ 50000
#define E_ 300
#define T_ 512
#define U_ 256
#define G_ 768      // 3*U
#define B_ 64
#define C_ 20
#define M_ (B_*T_)  // 32768

// ---------------- static device scratch ----------------
__device__ float g_xw[2][(size_t)M_ * G_];        // input projections per direction
__device__ float g_h1[(size_t)M_ * 2 * U_];       // layer1 h history [B][T][2U]  (write-once/launch)
__device__ float g_h2f[(size_t)2 * B_ * T_ * U_]; // layer2 h history [dir][B][T][U] (write-once/launch)
__device__ float g_h2[B_][2 * U_];                // final states
__device__ unsigned g_flg[2][2][4][T_];           // per-step arrival flags [layer][dir][bblk][step]

__device__ __forceinline__ uint32_t smem_u32(const void* p) {
    uint32_t a;
    asm("{ .reg .u64 t; cvta.to.shared.u64 t, %1; cvt.u32.u64 %0, t; }" : "=r"(a) : "l"(p));
    return a;
}
__device__ __forceinline__ void mma_tf32_16n8k8(float* c, const uint32_t* a, const uint32_t* b) {
    asm volatile(
        "mma.sync.aligned.m16n8k8.row.col.f32.tf32.tf32.f32 "
        "{%0,%1,%2,%3}, {%4,%5,%6,%7}, {%8,%9}, {%0,%1,%2,%3};"
        : "+f"(c[0]), "+f"(c[1]), "+f"(c[2]), "+f"(c[3])
        : "r"(a[0]), "r"(a[1]), "r"(a[2]), "r"(a[3]), "r"(b[0]), "r"(b[1]));
}
__device__ __forceinline__ float4 ldcg_f4(const float4* p) {
    float4 v;
    asm volatile("ld.global.cg.v4.f32 {%0,%1,%2,%3}, [%4];"
                 : "=f"(v.x), "=f"(v.y), "=f"(v.z), "=f"(v.w) : "l"(p) : "memory");
    return v;
}
__device__ __forceinline__ void stcg_f(float* p, float v) {
    asm volatile("st.global.cg.f32 [%0], %1;" :: "l"(p), "f"(v) : "memory");
}
__device__ __forceinline__ unsigned ld_acq(const unsigned* p) {
    unsigned v;
    asm volatile("ld.acquire.gpu.global.u32 %0, [%1];" : "=r"(v) : "l"(p) : "memory");
    return v;
}
__device__ __forceinline__ void red_rel_add(unsigned* p, unsigned v) {
    asm volatile("red.release.gpu.global.add.u32 [%0], %1;" :: "l"(p), "r"(v) : "memory");
}
#define CP_COMMIT() asm volatile("cp.async.commit_group;" ::: "memory")
#define CP_WAIT(n)  asm volatile("cp.async.wait_group %0;" :: "n"(n) : "memory")

// ---------------- reset flags (16KB) ----------------
__global__ void reset_k() {
    unsigned* f = &g_flg[0][0][0][0];
    const int n = 2 * 2 * 4 * T_;
    for (int i = threadIdx.x + blockIdx.x * blockDim.x; i < n; i += blockDim.x * gridDim.x)
        f[i] = 0u;
}

// ---------------- tf32 mma.sync GEMM, cp.async double-buffered, both dirs in one launch ----------------
#define SA_ 36
#define SB_ 136
#define A_FLOATS (128 * SA_)
#define B_FLOATS (32 * SB_)
#define BUF_FLOATS (A_FLOATS + B_FLOATS)
#define GEMM_SMEM (2 * BUF_FLOATS * 4)

__device__ __forceinline__ void stage_tile(
    uint32_t sa, uint32_t sb, const float* __restrict__ arow_p,
    const float* __restrict__ W, int n0, int k0, int Kreal, int tid)
{
    {
        int aseg0 = (tid & 1) * 4;
        int arow  = tid >> 1;
#pragma unroll
        for (int q = 0; q < 4; q++) {
            int col = k0 + (aseg0 + q) * 4;
            int szf = Kreal - col; szf = szf < 0 ? 0 : (szf > 4 ? 4 : szf);
            int sz = szf * 4;
            const float* src = arow_p + (sz ? col : 0);
            uint32_t dst = sa + (uint32_t)(arow * SA_ + (aseg0 + q) * 4) * 4u;
            asm volatile("cp.async.cg.shared.global [%0], [%1], 16, %2;"
                         :: "r"(dst), "l"(src), "r"(sz) : "memory");
        }
    }
    {
        int krow  = tid >> 3;
        int bseg0 = (tid & 7) * 4;
        int kr = k0 + krow;
        int sz = (kr < Kreal) ? 16 : 0;
        const float* brow_p = W + (size_t)(sz ? kr : 0) * G_ + n0;
#pragma unroll
        for (int q = 0; q < 4; q++) {
            uint32_t dst = sb + (uint32_t)(krow * SB_ + (bseg0 + q) * 4) * 4u;
            asm volatile("cp.async.cg.shared.global [%0], [%1], 16, %2;"
                         :: "r"(dst), "l"(brow_p + (bseg0 + q) * 4), "r"(sz) : "memory");
        }
    }
}

__global__ void __launch_bounds__(256, 2) mma_gemm_k(
    const float* __restrict__ A,
    const float* __restrict__ W0, const float* __restrict__ W1,
    const float* __restrict__ bias0, const float* __restrict__ bias1,
    float* __restrict__ C0, float* __restrict__ C1,
    int Kreal, const int* __restrict__ xidx)
{
    extern __shared__ float smf[];
    const uint32_t sbase = smem_u32(smf);

    const float* W    = blockIdx.z ? W1 : W0;
    const float* bias = blockIdx.z ? bias1 : bias0;
    float*       Cc   = blockIdx.z ? C1 : C0;

    const int tid  = threadIdx.x;
    const int wid  = tid >> 5;
    const int lane = tid & 31;
    const int lq   = lane & 3;
    const int gid  = lane >> 2;
    const int m0 = blockIdx.y * 128;
    const int n0 = blockIdx.x * 128;
    const int m0w = (wid & 3) * 32;
    const int n0w = (wid >> 2) * 64;

    const int arow = tid >> 1;
    const int ridx = xidx ? __ldg(&xidx[m0 + arow]) : (m0 + arow);
    const float* arow_p = A + (size_t)ridx * Kreal;

    float2 bv[8];
#pragma unroll
    for (int nt = 0; nt < 8; nt++)
        bv[nt] = *(const float2*)&bias[n0 + n0w + nt * 8 + lq * 2];

    float cfr[2][8][4];
#pragma unroll
    for (int mt = 0; mt < 2; mt++)
#pragma unroll
        for (int nt = 0; nt < 8; nt++)
#pragma unroll
            for (int j = 0; j < 4; j++) cfr[mt][nt][j] = 0.f;

    const int KT = (Kreal + 31) >> 5;

    stage_tile(sbase, sbase + A_FLOATS * 4u, arow_p, W, n0, 0, Kreal, tid);
    CP_COMMIT();

    for (int kt = 0; kt < KT; kt++) {
        const int cur = kt & 1;
        if (kt + 1 < KT) {
            uint32_t nb = sbase + (uint32_t)(((kt + 1) & 1) * BUF_FLOATS) * 4u;
            stage_tile(nb, nb + A_FLOATS * 4u, arow_p, W, n0, (kt + 1) << 5, Kreal, tid);
            CP_COMMIT();
            CP_WAIT(1);
        } else {
            CP_WAIT(0);
        }
        __syncthreads();

        const float* As_ = smf + cur * BUF_FLOATS;
        const float* Bs_ = As_ + A_FLOATS;

#pragma unroll
        for (int ks = 0; ks < 4; ks++) {
            const int kb = ks * 8;
            uint32_t af[2][4], bf[8][2];
#pragma unroll
            for (int mt = 0; mt < 2; mt++) {
                const float* ap = As_ + (m0w + mt * 16 + gid) * SA_ + kb + lq;
                af[mt][0] = __float_as_uint(ap[0]);
                af[mt][1] = __float_as_uint(ap[8 * SA_]);
                af[mt][2] = __float_as_uint(ap[4]);
                af[mt][3] = __float_as_uint(ap[8 * SA_ + 4]);
            }
#pragma unroll
            for (int nt = 0; nt < 8; nt++) {
                const float* bp = Bs_ + (kb + lq) * SB_ + n0w + nt * 8 + gid;
                bf[nt][0] = __float_as_uint(bp[0]);
                bf[nt][1] = __float_as_uint(bp[4 * SB_]);
            }
#pragma unroll
            for (int mt = 0; mt < 2; mt++)
#pragma unroll
                for (int nt = 0; nt < 8; nt++)
                    mma_tf32_16n8k8(cfr[mt][nt], af[mt], bf[nt]);
        }
        __syncthreads();
    }

#pragma unroll
    for (int mt = 0; mt < 2; mt++) {
        int row = m0 + m0w + mt * 16 + gid;
#pragma unroll
        for (int nt = 0; nt < 8; nt++) {
            int col = n0 + n0w + nt * 8 + lq * 2;
            float2 v0, v1;
            v0.x = cfr[mt][nt][0] + bv[nt].x;
            v0.y = cfr[mt][nt][1] + bv[nt].y;
            v1.x = cfr[mt][nt][2] + bv[nt].x;
            v1.y = cfr[mt][nt][3] + bv[nt].y;
            *(float2*)&Cc[(size_t)row * G_ + col] = v0;
            *(float2*)&Cc[(size_t)(row + 8) * G_ + col] = v1;
        }
    }
}

// ---------------- persistent bidirectional GRU scan ----------------
// grid = 64 CTAs: dir(2) x bblk(4, 16 batches) x ublk(8, 32 units). block = 512 (16 warps).
// Data path = R11 (coalesced float4 staging -> smem -> conflict-free LDS fragments).
// Sync = per-step flag: tid0 red.release.add(flg[s]); tid0 polls ld.acquire(flg[s-1])==8.
// hprev lives in a register; partials single-buffered (4 BARs/step).
#define HS_STRIDE 260
#define PT_STRIDE 100
__global__ void __launch_bounds__(512, 1) scan_k(
    const float* __restrict__ rkf, const float* __restrict__ rbf,
    const float* __restrict__ rkb, const float* __restrict__ rbb,
    int layer)
{
    __shared__ float hs[16 * HS_STRIDE];         // h_prev [16 batches][256k + pad]
    __shared__ float part[4 * 16 * PT_STRIDE];   // [kg][16 m][96 cols + pad]

    const int cta  = blockIdx.x;
    const int dir  = cta >> 5;
    const int bblk = (cta >> 3) & 3;
    const int ublk = cta & 7;
    const int b0 = bblk * 16, u0 = ublk * 32;
    const int tid  = threadIdx.x;
    const int wid  = tid >> 5;
    const int lane = tid & 31;
    const int lq   = lane & 3;
    const int gid  = lane >> 2;
    const int kg   = wid & 3;
    const int ng   = wid >> 2;

    const float* rk = dir ? rkb : rkf;
    const float* rb = dir ? rbb : rbf;
    const float* xw = g_xw[dir];
    unsigned* flg = &g_flg[layer - 1][dir][bblk][0];

    // recurrent-weight B fragments in registers (once)
    uint32_t bw[3][8][2];
#pragma unroll
    for (int nt = 0; nt < 3; nt++) {
        int c = ng * 24 + nt * 8 + gid;
        int ncol = (c >> 5) * U_ + u0 + (c & 31);
#pragma unroll
        for (int kt = 0; kt < 8; kt++) {
            int kb = kg * 64 + kt * 8 + lq;
            bw[nt][kt][0] = __float_as_uint(__ldg(&rk[(size_t)kb * G_ + ncol]));
            bw[nt][kt][1] = __float_as_uint(__ldg(&rk[(size_t)(kb + 4) * G_ + ncol]));
        }
    }

    // gate role: thread -> (batch wid, unit lane); hprev in a register
    const float bz  = rb[u0 + lane];
    const float brr = rb[U_ + u0 + lane];
    const float bh  = rb[2 * U_ + u0 + lane];
    float hprev = 0.f;

    for (int s = 0; s < T_; s++) {
        const int t = dir ? (T_ - 1 - s) : s;

        // ---- stage prev h into hs[b][k] (coalesced float4) ----
        if (s == 0) {
            for (int i = tid; i < 16 * HS_STRIDE; i += 512) hs[i] = 0.f;
        } else {
            const int tp = dir ? (t + 1) : (t - 1);
#pragma unroll
            for (int q = 0; q < 2; q++) {
                int idx = tid + q * 512;            // 0..1023
                int bb = idx >> 6, kf = idx & 63;
                float4 v;
                if (layer == 1) {
                    v = ldcg_f4((const float4*)&g_h1[((size_t)(b0 + bb) * T_ + tp) * (2 * U_) + dir * U_ + kf * 4]);
                } else {
                    v = ldcg_f4((const float4*)&g_h2f[((size_t)(dir * B_ + b0 + bb) * T_ + tp) * U_ + kf * 4]);
                }
                *(float4*)&hs[bb * HS_STRIDE + kf * 4] = v;
            }
        }

        // prefetch xw for gate phase (latency hidden under dot)
        const float* xwp = xw + ((size_t)(b0 + wid) * T_ + t) * G_;
        float xz = __ldg(xwp + u0 + lane);
        float xr = __ldg(xwp + U_ + u0 + lane);
        float xh = __ldg(xwp + 2 * U_ + u0 + lane);
        __syncthreads();

        // ---- tensor-core partial dot: h[16, kg-slice] @ rk[kg-slice, ng-cols] ----
        {
            float acc[3][4];
#pragma unroll
            for (int nt = 0; nt < 3; nt++)
#pragma unroll
                for (int j = 0; j < 4; j++) acc[nt][j] = 0.f;

#pragma unroll
            for (int kt = 0; kt < 8; kt++) {
                const int kb = kg * 64 + kt * 8;
                uint32_t af[4];
                af[0] = __float_as_uint(hs[gid * HS_STRIDE + kb + lq]);
                af[1] = __float_as_uint(hs[(gid + 8) * HS_STRIDE + kb + lq]);
                af[2] = __float_as_uint(hs[gid * HS_STRIDE + kb + lq + 4]);
                af[3] = __float_as_uint(hs[(gid + 8) * HS_STRIDE + kb + lq + 4]);
#pragma unroll
                for (int nt = 0; nt < 3; nt++)
                    mma_tf32_16n8k8(acc[nt], af, bw[nt][kt]);
            }

            float* pp = part + kg * (16 * PT_STRIDE);
#pragma unroll
            for (int nt = 0; nt < 3; nt++) {
                int colb = ng * 24 + nt * 8 + 2 * lq;
                *(float2*)&pp[gid * PT_STRIDE + colb]       = make_float2(acc[nt][0], acc[nt][1]);
                *(float2*)&pp[(gid + 8) * PT_STRIDE + colb] = make_float2(acc[nt][2], acc[nt][3]);
            }
        }
        __syncthreads();

        // ---- gates: thread (wid, lane) ----
        {
            float az = bz, ar = brr, ah = bh;
#pragma unroll
            for (int k4 = 0; k4 < 4; k4++) {
                const float* pp = part + k4 * (16 * PT_STRIDE) + wid * PT_STRIDE;
                az += pp[lane];
                ar += pp[32 + lane];
                ah += pp[64 + lane];
            }
            float z  = 1.f / (1.f + expf(-(xz + az)));
            float rg = 1.f / (1.f + expf(-(xr + ar)));
            float hh = tanhf(xh + rg * ah);
            float hn = z * hprev + (1.f - z) * hh;
            hprev = hn;
            if (layer == 1) {
                stcg_f(&g_h1[((size_t)(b0 + wid) * T_ + t) * (2 * U_) + dir * U_ + u0 + lane], hn);
            } else {
                stcg_f(&g_h2f[((size_t)(dir * B_ + b0 + wid) * T_ + t) * U_ + u0 + lane], hn);
                if (s == T_ - 1) g_h2[b0 + wid][dir * U_ + u0 + lane] = hn;
            }
        }

        // ---- publish + wait (single poller, release/acquire) ----
        if (s != T_ - 1) {
            __syncthreads();                       // all h stores issued
            if (tid == 0) {
                red_rel_add(flg + s, 1u);          // release: publish step s
                unsigned f;
                do { f = ld_acq(flg + s); } while (f < 8u);   // wait whole group
            }
            __syncthreads();
        }
    }
}

// ---------------- head: softmax(h2 @ wout + bout) ----------------
__global__ void head_k(const float* __restrict__ wout, const float* __restrict__ bout,
                       float* __restrict__ out)
{
    const int b = blockIdx.x, lane = threadIdx.x;
    float acc = 0.f;
    if (lane < C_) {
        acc = bout[lane];
        for (int k = 0; k < 2 * U_; k++)
            acc = fmaf(g_h2[b][k], wout[k * C_ + lane], acc);
    }
    float v = (lane < C_) ? acc : -INFINITY;
    for (int o = 16; o; o >>= 1) v = fmaxf(v, __shfl_xor_sync(0xffffffffu, v, o));
    float e = (lane < C_) ? expf(acc - v) : 0.f;
    float ssum = e;
    for (int o = 16; o; o >>= 1) ssum += __shfl_xor_sync(0xffffffffu, ssum, o);
    if (lane < C_) out[b * C_ + lane] = e / ssum;
}

// ---------------- launch ----------------
extern "C" void kernel_launch(void* const* d_in, const int* in_sizes, int n_in,
                              void* d_out, int out_size)
{
    const int*   x    = (const int*)  d_in[0];
    const float* emb  = (const float*)d_in[1];
    const float* k1f  = (const float*)d_in[2];
    const float* rk1f = (const float*)d_in[3];
    const float* b1f  = (const float*)d_in[4];
    const float* k1b  = (const float*)d_in[5];
    const float* rk1b = (const float*)d_in[6];
    const float* b1b  = (const float*)d_in[7];
    const float* k2f  = (const float*)d_in[8];
    const float* rk2f = (const float*)d_in[9];
    const float* b2f  = (const float*)d_in[10];
    const float* k2b  = (const float*)d_in[11];
    const float* rk2b = (const float*)d_in[12];
    const float* b2b  = (const float*)d_in[13];
    const float* wout = (const float*)d_in[14];
    const float* bout = (const float*)d_in[15];
    float* out = (float*)d_out;

    float *pxw0, *pxw1, *ph1;
    cudaGetSymbolAddress((void**)&pxw0, g_xw);
    pxw1 = pxw0 + (size_t)M_ * G_;
    cudaGetSymbolAddress((void**)&ph1,  g_h1);

    cudaFuncSetAttribute(mma_gemm_k, cudaFuncAttributeMaxDynamicSharedMemorySize, GEMM_SMEM);

    dim3 gg(G_ / 128, M_ / 128, 2);   // (6, 256, dir)

    // 0) reset per-step flags
    reset_k<<<8, 512>>>();

    // 1) layer-1 input projections, both dirs in one launch, gather fused
    mma_gemm_k<<<gg, 256, GEMM_SMEM>>>(emb, k1f, k1b, b1f, b1b, pxw0, pxw1, E_, x);

    // 2) layer-1 bidirectional scan -> g_h1
    scan_k<<<64, 512>>>(rk1f, b1f + G_, rk1b, b1b + G_, 1);

    // 3) layer-2 input projections, both dirs
    mma_gemm_k<<<gg, 256, GEMM_SMEM>>>(ph1, k2f, k2b, b2f, b2b, pxw0, pxw1, 2 * U_, (const int*)nullptr);

    // 4) layer-2 bidirectional scan -> g_h2
    scan_k<<<64, 512>>>(rk2f, b2f + G_, rk2b, b2b + G_, 2);

    // 5) output head
    head_k<<<B_, 32>>>(wout, bout, out);
}

// round 16
// speedup vs baseline: 1.2955x; 1.0210x over previous
#include <cuda_runtime.h>
#include <math.h>
#include <stdint.h>

// Problem constants
#define V_ 50000
#define E_ 300
#define T_ 512
#define U_ 256
#define G_ 768      // 3*U
#define B_ 64
#define C_ 20
#define M_ (B_*T_)  // 32768

// ---------------- static device scratch ----------------
__device__ float g_xw[2][(size_t)M_ * G_];        // input projections per direction
__device__ float g_h1[(size_t)M_ * 2 * U_];       // layer1 h history [B][T][2U]  (write-once/launch)
__device__ float g_h2f[(size_t)2 * B_ * T_ * U_]; // layer2 h history [dir][B][T][U] (write-once/launch)
__device__ float g_h2[B_][2 * U_];                // final states
__device__ unsigned g_flg[2][2][4][T_];           // per-step arrival flags [layer][dir][bblk][step]

__device__ __forceinline__ uint32_t smem_u32(const void* p) {
    uint32_t a;
    asm("{ .reg .u64 t; cvta.to.shared.u64 t, %1; cvt.u32.u64 %0, t; }" : "=r"(a) : "l"(p));
    return a;
}
__device__ __forceinline__ void mma_tf32_16n8k8(float* c, const uint32_t* a, const uint32_t* b) {
    asm volatile(
        "mma.sync.aligned.m16n8k8.row.col.f32.tf32.tf32.f32 "
        "{%0,%1,%2,%3}, {%4,%5,%6,%7}, {%8,%9}, {%0,%1,%2,%3};"
        : "+f"(c[0]), "+f"(c[1]), "+f"(c[2]), "+f"(c[3])
        : "r"(a[0]), "r"(a[1]), "r"(a[2]), "r"(a[3]), "r"(b[0]), "r"(b[1]));
}
__device__ __forceinline__ float4 ldcg_f4(const float4* p) {
    float4 v;
    asm volatile("ld.global.cg.v4.f32 {%0,%1,%2,%3}, [%4];"
                 : "=f"(v.x), "=f"(v.y), "=f"(v.z), "=f"(v.w) : "l"(p) : "memory");
    return v;
}
__device__ __forceinline__ void stcg_f(float* p, float v) {
    asm volatile("st.global.cg.f32 [%0], %1;" :: "l"(p), "f"(v) : "memory");
}
__device__ __forceinline__ unsigned ld_acq(const unsigned* p) {
    unsigned v;
    asm volatile("ld.acquire.gpu.global.u32 %0, [%1];" : "=r"(v) : "l"(p) : "memory");
    return v;
}
__device__ __forceinline__ void red_rel_add(unsigned* p, unsigned v) {
    asm volatile("red.release.gpu.global.add.u32 [%0], %1;" :: "l"(p), "r"(v) : "memory");
}
#define CP_COMMIT() asm volatile("cp.async.commit_group;" ::: "memory")
#define CP_WAIT(n)  asm volatile("cp.async.wait_group %0;" :: "n"(n) : "memory")

// ---------------- reset flags (16KB) ----------------
__global__ void reset_k() {
    unsigned* f = &g_flg[0][0][0][0];
    const int n = 2 * 2 * 4 * T_;
    for (int i = threadIdx.x + blockIdx.x * blockDim.x; i < n; i += blockDim.x * gridDim.x)
        f[i] = 0u;
}

// ---------------- tf32 mma.sync GEMM, cp.async double-buffered, both dirs in one launch ----------------
#define SA_ 36
#define SB_ 136
#define A_FLOATS (128 * SA_)
#define B_FLOATS (32 * SB_)
#define BUF_FLOATS (A_FLOATS + B_FLOATS)
#define GEMM_SMEM (2 * BUF_FLOATS * 4)

__device__ __forceinline__ void stage_tile(
    uint32_t sa, uint32_t sb, const float* __restrict__ arow_p,
    const float* __restrict__ W, int n0, int k0, int Kreal, int tid)
{
    {
        int aseg0 = (tid & 1) * 4;
        int arow  = tid >> 1;
#pragma unroll
        for (int q = 0; q < 4; q++) {
            int col = k0 + (aseg0 + q) * 4;
            int szf = Kreal - col; szf = szf < 0 ? 0 : (szf > 4 ? 4 : szf);
            int sz = szf * 4;
            const float* src = arow_p + (sz ? col : 0);
            uint32_t dst = sa + (uint32_t)(arow * SA_ + (aseg0 + q) * 4) * 4u;
            asm volatile("cp.async.cg.shared.global [%0], [%1], 16, %2;"
                         :: "r"(dst), "l"(src), "r"(sz) : "memory");
        }
    }
    {
        int krow  = tid >> 3;
        int bseg0 = (tid & 7) * 4;
        int kr = k0 + krow;
        int sz = (kr < Kreal) ? 16 : 0;
        const float* brow_p = W + (size_t)(sz ? kr : 0) * G_ + n0;
#pragma unroll
        for (int q = 0; q < 4; q++) {
            uint32_t dst = sb + (uint32_t)(krow * SB_ + (bseg0 + q) * 4) * 4u;
            asm volatile("cp.async.cg.shared.global [%0], [%1], 16, %2;"
                         :: "r"(dst), "l"(brow_p + (bseg0 + q) * 4), "r"(sz) : "memory");
        }
    }
}

__global__ void __launch_bounds__(256, 2) mma_gemm_k(
    const float* __restrict__ A,
    const float* __restrict__ W0, const float* __restrict__ W1,
    const float* __restrict__ bias0, const float* __restrict__ bias1,
    float* __restrict__ C0, float* __restrict__ C1,
    int Kreal, const int* __restrict__ xidx)
{
    extern __shared__ float smf[];
    const uint32_t sbase = smem_u32(smf);

    const float* W    = blockIdx.z ? W1 : W0;
    const float* bias = blockIdx.z ? bias1 : bias0;
    float*       Cc   = blockIdx.z ? C1 : C0;

    const int tid  = threadIdx.x;
    const int wid  = tid >> 5;
    const int lane = tid & 31;
    const int lq   = lane & 3;
    const int gid  = lane >> 2;
    const int m0 = blockIdx.y * 128;
    const int n0 = blockIdx.x * 128;
    const int m0w = (wid & 3) * 32;
    const int n0w = (wid >> 2) * 64;

    const int arow = tid >> 1;
    const int ridx = xidx ? __ldg(&xidx[m0 + arow]) : (m0 + arow);
    const float* arow_p = A + (size_t)ridx * Kreal;

    float2 bv[8];
#pragma unroll
    for (int nt = 0; nt < 8; nt++)
        bv[nt] = *(const float2*)&bias[n0 + n0w + nt * 8 + lq * 2];

    float cfr[2][8][4];
#pragma unroll
    for (int mt = 0; mt < 2; mt++)
#pragma unroll
        for (int nt = 0; nt < 8; nt++)
#pragma unroll
            for (int j = 0; j < 4; j++) cfr[mt][nt][j] = 0.f;

    const int KT = (Kreal + 31) >> 5;

    stage_tile(sbase, sbase + A_FLOATS * 4u, arow_p, W, n0, 0, Kreal, tid);
    CP_COMMIT();

    for (int kt = 0; kt < KT; kt++) {
        const int cur = kt & 1;
        if (kt + 1 < KT) {
            uint32_t nb = sbase + (uint32_t)(((kt + 1) & 1) * BUF_FLOATS) * 4u;
            stage_tile(nb, nb + A_FLOATS * 4u, arow_p, W, n0, (kt + 1) << 5, Kreal, tid);
            CP_COMMIT();
            CP_WAIT(1);
        } else {
            CP_WAIT(0);
        }
        __syncthreads();

        const float* As_ = smf + cur * BUF_FLOATS;
        const float* Bs_ = As_ + A_FLOATS;

#pragma unroll
        for (int ks = 0; ks < 4; ks++) {
            const int kb = ks * 8;
            uint32_t af[2][4], bf[8][2];
#pragma unroll
            for (int mt = 0; mt < 2; mt++) {
                const float* ap = As_ + (m0w + mt * 16 + gid) * SA_ + kb + lq;
                af[mt][0] = __float_as_uint(ap[0]);
                af[mt][1] = __float_as_uint(ap[8 * SA_]);
                af[mt][2] = __float_as_uint(ap[4]);
                af[mt][3] = __float_as_uint(ap[8 * SA_ + 4]);
            }
#pragma unroll
            for (int nt = 0; nt < 8; nt++) {
                const float* bp = Bs_ + (kb + lq) * SB_ + n0w + nt * 8 + gid;
                bf[nt][0] = __float_as_uint(bp[0]);
                bf[nt][1] = __float_as_uint(bp[4 * SB_]);
            }
#pragma unroll
            for (int mt = 0; mt < 2; mt++)
#pragma unroll
                for (int nt = 0; nt < 8; nt++)
                    mma_tf32_16n8k8(cfr[mt][nt], af[mt], bf[nt]);
        }
        __syncthreads();
    }

#pragma unroll
    for (int mt = 0; mt < 2; mt++) {
        int row = m0 + m0w + mt * 16 + gid;
#pragma unroll
        for (int nt = 0; nt < 8; nt++) {
            int col = n0 + n0w + nt * 8 + lq * 2;
            float2 v0, v1;
            v0.x = cfr[mt][nt][0] + bv[nt].x;
            v0.y = cfr[mt][nt][1] + bv[nt].y;
            v1.x = cfr[mt][nt][2] + bv[nt].x;
            v1.y = cfr[mt][nt][3] + bv[nt].y;
            *(float2*)&Cc[(size_t)row * G_ + col] = v0;
            *(float2*)&Cc[(size_t)(row + 8) * G_ + col] = v1;
        }
    }
}

// ---------------- persistent bidirectional GRU scan — distributed per-warp sync ----------------
// grid = 64 CTAs: dir(2) x bblk(4, 16 batches) x ublk(8, 32 units). block = 512 (16 warps).
// Warp w owns batch w end-to-end: stages its h row, computes its gates, stores its h,
// and arrives (red.release, +1 of 128) on the per-step flag. Every warp wakes itself by
// polling ld.acquire(flag[s-1]) == 128. Only TWO __syncthreads per step (hs->dot, part->gates).
// Safety: flag==128 => all group warps issued h stores => all same-CTA warps passed sync_b
// => hs and part of the previous step are dead; gates read neither hs nor flag state.
#define HS_STRIDE 260
#define PT_STRIDE 100
__global__ void __launch_bounds__(512, 1) scan_k(
    const float* __restrict__ rkf, const float* __restrict__ rbf,
    const float* __restrict__ rkb, const float* __restrict__ rbb,
    int layer)
{
    __shared__ float hs[16 * HS_STRIDE];         // h_prev [16 batches][256k + pad]
    __shared__ float part[4 * 16 * PT_STRIDE];   // [kg][16 m][96 cols + pad]

    const int cta  = blockIdx.x;
    const int dir  = cta >> 5;
    const int bblk = (cta >> 3) & 3;
    const int ublk = cta & 7;
    const int b0 = bblk * 16, u0 = ublk * 32;
    const int tid  = threadIdx.x;
    const int wid  = tid >> 5;
    const int lane = tid & 31;
    const int lq   = lane & 3;
    const int gid  = lane >> 2;
    const int kg   = wid & 3;
    const int ng   = wid >> 2;

    const float* rk = dir ? rkb : rkf;
    const float* rb = dir ? rbb : rbf;
    const float* xw = g_xw[dir];
    unsigned* flg = &g_flg[layer - 1][dir][bblk][0];

    // recurrent-weight B fragments in registers (once)
    uint32_t bw[3][8][2];
#pragma unroll
    for (int nt = 0; nt < 3; nt++) {
        int c = ng * 24 + nt * 8 + gid;
        int ncol = (c >> 5) * U_ + u0 + (c & 31);
#pragma unroll
        for (int kt = 0; kt < 8; kt++) {
            int kb = kg * 64 + kt * 8 + lq;
            bw[nt][kt][0] = __float_as_uint(__ldg(&rk[(size_t)kb * G_ + ncol]));
            bw[nt][kt][1] = __float_as_uint(__ldg(&rk[(size_t)(kb + 4) * G_ + ncol]));
        }
    }

    // gate role: warp wid owns batch b0+wid, lane = unit; hprev in a register
    const float bz  = rb[u0 + lane];
    const float brr = rb[U_ + u0 + lane];
    const float bh  = rb[2 * U_ + u0 + lane];
    float hprev = 0.f;

    // h row base for this warp's OWN batch (producer side)
    float* myrow_t0;   // recomputed per step below

    // zero hs for step 0
    for (int i = tid; i < 16 * HS_STRIDE; i += 512) hs[i] = 0.f;
    __syncthreads();

    for (int s = 0; s < T_; s++) {
        const int t = dir ? (T_ - 1 - s) : s;

        // ---- wait for step s-1 (all lanes poll same line: 1 broadcast L2 req/iter),
        //      then stage OWN batch's h row (2 coalesced float4 per lane) ----
        if (s > 0) {
            unsigned f;
            do { f = ld_acq(flg + (s - 1)); } while (f < 128u);
            const int tp = dir ? (t + 1) : (t - 1);
            const float4* src;
            if (layer == 1)
                src = (const float4*)&g_h1[((size_t)(b0 + wid) * T_ + tp) * (2 * U_) + dir * U_];
            else
                src = (const float4*)&g_h2f[((size_t)(dir * B_ + b0 + wid) * T_ + tp) * U_];
            float4 v0 = ldcg_f4(src + lane);
            float4 v1 = ldcg_f4(src + lane + 32);
            *(float4*)&hs[wid * HS_STRIDE + lane * 4] = v0;
            *(float4*)&hs[wid * HS_STRIDE + (lane + 32) * 4] = v1;
        }

        // prefetch xw for gate phase (latency hidden under dot)
        const float* xwp = xw + ((size_t)(b0 + wid) * T_ + t) * G_;
        float xz = __ldg(xwp + u0 + lane);
        float xr = __ldg(xwp + U_ + u0 + lane);
        float xh = __ldg(xwp + 2 * U_ + u0 + lane);
        __syncthreads();                      // sync_a: hs complete

        // ---- tensor-core partial dot: h[16, kg-slice] @ rk[kg-slice, ng-cols] ----
        {
            float acc[3][4];
#pragma unroll
            for (int nt = 0; nt < 3; nt++)
#pragma unroll
                for (int j = 0; j < 4; j++) acc[nt][j] = 0.f;

#pragma unroll
            for (int kt = 0; kt < 8; kt++) {
                const int kb = kg * 64 + kt * 8;
                uint32_t af[4];
                af[0] = __float_as_uint(hs[gid * HS_STRIDE + kb + lq]);
                af[1] = __float_as_uint(hs[(gid + 8) * HS_STRIDE + kb + lq]);
                af[2] = __float_as_uint(hs[gid * HS_STRIDE + kb + lq + 4]);
                af[3] = __float_as_uint(hs[(gid + 8) * HS_STRIDE + kb + lq + 4]);
#pragma unroll
                for (int nt = 0; nt < 3; nt++)
                    mma_tf32_16n8k8(acc[nt], af, bw[nt][kt]);
            }

            float* pp = part + kg * (16 * PT_STRIDE);
#pragma unroll
            for (int nt = 0; nt < 3; nt++) {
                int colb = ng * 24 + nt * 8 + 2 * lq;
                *(float2*)&pp[gid * PT_STRIDE + colb]       = make_float2(acc[nt][0], acc[nt][1]);
                *(float2*)&pp[(gid + 8) * PT_STRIDE + colb] = make_float2(acc[nt][2], acc[nt][3]);
            }
        }
        __syncthreads();                      // sync_b: part complete

        // ---- gates: warp wid computes batch b0+wid; store h; per-warp release ----
        {
            float az = bz, ar = brr, ah = bh;
#pragma unroll
            for (int k4 = 0; k4 < 4; k4++) {
                const float* pp = part + k4 * (16 * PT_STRIDE) + wid * PT_STRIDE;
                az += pp[lane];
                ar += pp[32 + lane];
                ah += pp[64 + lane];
            }
            float z  = 1.f / (1.f + expf(-(xz + az)));
            float rg = 1.f / (1.f + expf(-(xr + ar)));
            float hh = tanhf(xh + rg * ah);
            float hn = z * hprev + (1.f - z) * hh;
            hprev = hn;
            if (layer == 1) {
                stcg_f(&g_h1[((size_t)(b0 + wid) * T_ + t) * (2 * U_) + dir * U_ + u0 + lane], hn);
            } else {
                stcg_f(&g_h2f[((size_t)(dir * B_ + b0 + wid) * T_ + t) * U_ + u0 + lane], hn);
                if (s == T_ - 1) g_h2[b0 + wid][dir * U_ + u0 + lane] = hn;
            }
        }
        if (s != T_ - 1 && lane == 0)
            red_rel_add(flg + s, 1u);         // warp-level arrive: release own h stores
    }
}

// ---------------- head: softmax(h2 @ wout + bout) ----------------
__global__ void head_k(const float* __restrict__ wout, const float* __restrict__ bout,
                       float* __restrict__ out)
{
    const int b = blockIdx.x, lane = threadIdx.x;
    float acc = 0.f;
    if (lane < C_) {
        acc = bout[lane];
        for (int k = 0; k < 2 * U_; k++)
            acc = fmaf(g_h2[b][k], wout[k * C_ + lane], acc);
    }
    float v = (lane < C_) ? acc : -INFINITY;
    for (int o = 16; o; o >>= 1) v = fmaxf(v, __shfl_xor_sync(0xffffffffu, v, o));
    float e = (lane < C_) ? expf(acc - v) : 0.f;
    float ssum = e;
    for (int o = 16; o; o >>= 1) ssum += __shfl_xor_sync(0xffffffffu, ssum, o);
    if (lane < C_) out[b * C_ + lane] = e / ssum;
}

// ---------------- launch ----------------
extern "C" void kernel_launch(void* const* d_in, const int* in_sizes, int n_in,
                              void* d_out, int out_size)
{
    const int*   x    = (const int*)  d_in[0];
    const float* emb  = (const float*)d_in[1];
    const float* k1f  = (const float*)d_in[2];
    const float* rk1f = (const float*)d_in[3];
    const float* b1f  = (const float*)d_in[4];
    const float* k1b  = (const float*)d_in[5];
    const float* rk1b = (const float*)d_in[6];
    const float* b1b  = (const float*)d_in[7];
    const float* k2f  = (const float*)d_in[8];
    const float* rk2f = (const float*)d_in[9];
    const float* b2f  = (const float*)d_in[10];
    const float* k2b  = (const float*)d_in[11];
    const float* rk2b = (const float*)d_in[12];
    const float* b2b  = (const float*)d_in[13];
    const float* wout = (const float*)d_in[14];
    const float* bout = (const float*)d_in[15];
    float* out = (float*)d_out;

    float *pxw0, *pxw1, *ph1;
    cudaGetSymbolAddress((void**)&pxw0, g_xw);
    pxw1 = pxw0 + (size_t)M_ * G_;
    cudaGetSymbolAddress((void**)&ph1,  g_h1);

    cudaFuncSetAttribute(mma_gemm_k, cudaFuncAttributeMaxDynamicSharedMemorySize, GEMM_SMEM);

    dim3 gg(G_ / 128, M_ / 128, 2);   // (6, 256, dir)

    // 0) reset per-step flags
    reset_k<<<8, 512>>>();

    // 1) layer-1 input projections, both dirs in one launch, gather fused
    mma_gemm_k<<<gg, 256, GEMM_SMEM>>>(emb, k1f, k1b, b1f, b1b, pxw0, pxw1, E_, x);

    // 2) layer-1 bidirectional scan -> g_h1
    scan_k<<<64, 512>>>(rk1f, b1f + G_, rk1b, b1b + G_, 1);

    // 3) layer-2 input projections, both dirs
    mma_gemm_k<<<gg, 256, GEMM_SMEM>>>(ph1, k2f, k2b, b2f, b2b, pxw0, pxw1, 2 * U_, (const int*)nullptr);

    // 4) layer-2 bidirectional scan -> g_h2
    scan_k<<<64, 512>>>(rk2f, b2f + G_, rk2b, b2b + G_, 2);

    // 5) output head
    head_k<<<B_, 32>>>(wout, bout, out);
}